// round 1
// baseline (speedup 1.0000x reference)
#include <cuda_runtime.h>

#define NN     50000
#define EE     100000
#define KNB    8
#define DNODE  64
#define DEDGE  64
#define NHEAD  4
#define DHEAD  16
#define DIN    192

// ---------------- scratch (device globals; no runtime allocation) ----------------
__device__ float g_x[EE * DIN];      // [E, 192] concat(edge_f, node_f[src], node_f[dst])
__device__ float g_qkv[EE * DIN];    // [E, 192] = [q(64) | k(64) | v(64)]
__device__ float g_att[EE * DEDGE];  // [E, 64] attention output
__device__ float g_ef1[EE * DEDGE];  // [E, 64] layer-1 output edge features
__device__ float g_w[DIN * DIN];     // [192, 192] concatenated [Wq | Wk | Wv]

// ---------------- build x = concat(ef, nf[src], nf[dst]) ----------------
__global__ void build_x_kernel(const float* __restrict__ ef, const float* __restrict__ nf,
                               const int* __restrict__ ei) {
    int idx = blockIdx.x * blockDim.x + threadIdx.x;   // float4 index
    if (idx >= EE * 48) return;
    int e = idx / 48;
    int c = idx - e * 48;
    float4 v;
    if (c < 16) {
        v = reinterpret_cast<const float4*>(ef + (size_t)e * DEDGE)[c];
    } else if (c < 32) {
        int s = ei[e];
        v = reinterpret_cast<const float4*>(nf + (size_t)s * DNODE)[c - 16];
    } else {
        int d = ei[EE + e];
        v = reinterpret_cast<const float4*>(nf + (size_t)d * DNODE)[c - 32];
    }
    reinterpret_cast<float4*>(g_x + (size_t)e * DIN)[c] = v;
}

// Rewrite only the edge-feature slice of x for layer 2 (node slices unchanged)
__global__ void update_x_kernel() {
    int idx = blockIdx.x * blockDim.x + threadIdx.x;   // float4 index into [E,64]
    if (idx >= EE * 16) return;
    int e = idx / 16;
    int c = idx - e * 16;
    reinterpret_cast<float4*>(g_x + (size_t)e * DIN)[c] =
        reinterpret_cast<const float4*>(g_ef1 + (size_t)e * DEDGE)[c];
}

// ---------------- concatenate Wq|Wk|Wv into a single [192,192] matrix ----------------
__global__ void concat_w_kernel(const float* __restrict__ wq, const float* __restrict__ wk,
                                const float* __restrict__ wv) {
    int idx = blockIdx.x * blockDim.x + threadIdx.x;
    if (idx >= DIN * DIN) return;
    int i = idx / DIN, j = idx - i * DIN;
    float v = (j < 64) ? wq[i * 64 + j]
            : (j < 128) ? wk[i * 64 + (j - 64)]
            : wv[i * 64 + (j - 128)];
    g_w[idx] = v;
}

// ---------------- QKV GEMM: g_qkv = g_x[E,192] @ g_w[192,192] ----------------
// BM=128, BN=64, BK=16, 256 threads, 8x4 micro-tile per thread
__global__ __launch_bounds__(256) void gemm_qkv_kernel() {
    __shared__ float As[16][128];
    __shared__ float Bs[16][64];
    const int m0 = blockIdx.x * 128;
    const int n0 = blockIdx.y * 64;
    const int tid = threadIdx.x;
    const int tx = tid & 15, ty = tid >> 4;

    float acc[8][4] = {};

    const int lr = tid >> 1;          // A load row 0..127
    const int lc = (tid & 1) * 8;     // A load col offset (0 or 8)
    const int br = tid >> 4;          // B load row 0..15
    const int bc = (tid & 15) * 4;    // B load col

    for (int k0 = 0; k0 < DIN; k0 += 16) {
        float4 a0, a1;
        if (m0 + lr < EE) {
            const float* ap = g_x + (size_t)(m0 + lr) * DIN + k0 + lc;
            a0 = *reinterpret_cast<const float4*>(ap);
            a1 = *reinterpret_cast<const float4*>(ap + 4);
        } else {
            a0 = make_float4(0.f, 0.f, 0.f, 0.f);
            a1 = a0;
        }
        As[lc + 0][lr] = a0.x; As[lc + 1][lr] = a0.y;
        As[lc + 2][lr] = a0.z; As[lc + 3][lr] = a0.w;
        As[lc + 4][lr] = a1.x; As[lc + 5][lr] = a1.y;
        As[lc + 6][lr] = a1.z; As[lc + 7][lr] = a1.w;

        *reinterpret_cast<float4*>(&Bs[br][bc]) =
            *reinterpret_cast<const float4*>(g_w + (size_t)(k0 + br) * DIN + n0 + bc);
        __syncthreads();

        #pragma unroll
        for (int k = 0; k < 16; k++) {
            float a[8], b4[4];
            *reinterpret_cast<float4*>(&a[0]) = *reinterpret_cast<const float4*>(&As[k][ty * 4]);
            *reinterpret_cast<float4*>(&a[4]) = *reinterpret_cast<const float4*>(&As[k][64 + ty * 4]);
            *reinterpret_cast<float4*>(&b4[0]) = *reinterpret_cast<const float4*>(&Bs[k][tx * 4]);
            #pragma unroll
            for (int i = 0; i < 8; i++)
                #pragma unroll
                for (int j = 0; j < 4; j++)
                    acc[i][j] += a[i] * b4[j];
        }
        __syncthreads();
    }

    #pragma unroll
    for (int i = 0; i < 8; i++) {
        int row = m0 + ((i < 4) ? (ty * 4 + i) : (64 + ty * 4 + (i - 4)));
        if (row < EE) {
            *reinterpret_cast<float4*>(g_qkv + (size_t)row * DIN + n0 + tx * 4) =
                *reinterpret_cast<float4*>(&acc[i][0]);
        }
    }
}

// ---------------- attention: one warp per dst edge, K=8 contiguous neighbors ----------------
__global__ void attn_kernel(const int* __restrict__ adj_src) {
    int gw = (blockIdx.x * blockDim.x + threadIdx.x) >> 5;
    int lane = threadIdx.x & 31;
    if (gw >= EE) return;

    // lane holds components 2*lane, 2*lane+1; head = (2*lane)/16 -> lanes [8h, 8h+8)
    const float* qrow = g_qkv + (size_t)gw * DIN;
    float2 q = *reinterpret_cast<const float2*>(qrow + 2 * lane);

    float sj[KNB], v0[KNB], v1[KNB];
    int base = gw * KNB;
    #pragma unroll
    for (int j = 0; j < KNB; j++) {
        int n = adj_src[base + j];
        const float* kr = g_qkv + (size_t)n * DIN + 64;
        float2 kk = *reinterpret_cast<const float2*>(kr + 2 * lane);
        float2 vv = *reinterpret_cast<const float2*>(kr + 64 + 2 * lane);
        float p = q.x * kk.x + q.y * kk.y;
        p += __shfl_xor_sync(0xffffffffu, p, 1);
        p += __shfl_xor_sync(0xffffffffu, p, 2);
        p += __shfl_xor_sync(0xffffffffu, p, 4);   // head-local reduce (8 lanes)
        sj[j] = p * 0.25f;                          // 1/sqrt(16)
        v0[j] = vv.x;
        v1[j] = vv.y;
    }

    float m = sj[0];
    #pragma unroll
    for (int j = 1; j < KNB; j++) m = fmaxf(m, sj[j]);

    float denom = 0.f, a0 = 0.f, a1 = 0.f;
    #pragma unroll
    for (int j = 0; j < KNB; j++) {
        float w = __expf(sj[j] - m);
        denom += w;
        a0 += w * v0[j];
        a1 += w * v1[j];
    }
    float inv = 1.0f / denom;
    float2 o;
    o.x = a0 * inv;
    o.y = a1 * inv;
    *reinterpret_cast<float2*>(g_att + (size_t)gw * DEDGE + 2 * lane) = o;
}

// ---------------- output GEMM: out = ef_in + g_att[E,64] @ Wo[64,64] ----------------
__global__ __launch_bounds__(256) void gemm_wo_kernel(const float* __restrict__ Wo,
                                                      const float* __restrict__ ef_in_ext,
                                                      float* __restrict__ out_ext,
                                                      int use_gef1_in, int write_gef1) {
    __shared__ float As[16][128];
    __shared__ float Bs[16][64];
    const int m0 = blockIdx.x * 128;
    const int tid = threadIdx.x;
    const int tx = tid & 15, ty = tid >> 4;
    const float* ef_in = use_gef1_in ? g_ef1 : ef_in_ext;
    float* out = write_gef1 ? g_ef1 : out_ext;

    float acc[8][4] = {};

    const int lr = tid >> 1;
    const int lc = (tid & 1) * 8;
    const int br = tid >> 4;
    const int bc = (tid & 15) * 4;

    for (int k0 = 0; k0 < 64; k0 += 16) {
        float4 a0, a1;
        if (m0 + lr < EE) {
            const float* ap = g_att + (size_t)(m0 + lr) * DEDGE + k0 + lc;
            a0 = *reinterpret_cast<const float4*>(ap);
            a1 = *reinterpret_cast<const float4*>(ap + 4);
        } else {
            a0 = make_float4(0.f, 0.f, 0.f, 0.f);
            a1 = a0;
        }
        As[lc + 0][lr] = a0.x; As[lc + 1][lr] = a0.y;
        As[lc + 2][lr] = a0.z; As[lc + 3][lr] = a0.w;
        As[lc + 4][lr] = a1.x; As[lc + 5][lr] = a1.y;
        As[lc + 6][lr] = a1.z; As[lc + 7][lr] = a1.w;

        *reinterpret_cast<float4*>(&Bs[br][bc]) =
            *reinterpret_cast<const float4*>(Wo + (size_t)(k0 + br) * 64 + bc);
        __syncthreads();

        #pragma unroll
        for (int k = 0; k < 16; k++) {
            float a[8], b4[4];
            *reinterpret_cast<float4*>(&a[0]) = *reinterpret_cast<const float4*>(&As[k][ty * 4]);
            *reinterpret_cast<float4*>(&a[4]) = *reinterpret_cast<const float4*>(&As[k][64 + ty * 4]);
            *reinterpret_cast<float4*>(&b4[0]) = *reinterpret_cast<const float4*>(&Bs[k][tx * 4]);
            #pragma unroll
            for (int i = 0; i < 8; i++)
                #pragma unroll
                for (int j = 0; j < 4; j++)
                    acc[i][j] += a[i] * b4[j];
        }
        __syncthreads();
    }

    #pragma unroll
    for (int i = 0; i < 8; i++) {
        int row = m0 + ((i < 4) ? (ty * 4 + i) : (64 + ty * 4 + (i - 4)));
        if (row < EE) {
            float4 r = *reinterpret_cast<const float4*>(ef_in + (size_t)row * DEDGE + tx * 4);
            float4 o;
            o.x = r.x + acc[i][0];
            o.y = r.y + acc[i][1];
            o.z = r.z + acc[i][2];
            o.w = r.w + acc[i][3];
            *reinterpret_cast<float4*>(out + (size_t)row * DEDGE + tx * 4) = o;
        }
    }
}

// ---------------- launch ----------------
extern "C" void kernel_launch(void* const* d_in, const int* in_sizes, int n_in,
                              void* d_out, int out_size) {
    const float* nf      = (const float*)d_in[0];   // node_features [N,64]
    const float* ef      = (const float*)d_in[1];   // edge_features [E,64]
    const int*   ei      = (const int*)d_in[2];     // edge_index [2,E]
    // d_in[3] = node_tiers (unused by reference)
    const int*   adj_src = (const int*)d_in[4];     // [E*K]
    // d_in[5] = adj_dst == repeat(arange(E),K) -> exploited as contiguous segments
    const float* l1_Wq = (const float*)d_in[6];
    const float* l1_Wk = (const float*)d_in[7];
    const float* l1_Wv = (const float*)d_in[8];
    const float* l1_Wo = (const float*)d_in[9];
    const float* l2_Wq = (const float*)d_in[10];
    const float* l2_Wk = (const float*)d_in[11];
    const float* l2_Wv = (const float*)d_in[12];
    const float* l2_Wo = (const float*)d_in[13];
    float* out = (float*)d_out;

    const dim3 gqkv((EE + 127) / 128, 3);
    const dim3 gwo((EE + 127) / 128, 1);
    const int attn_blocks = EE / 8;   // 8 warps (edges) per 256-thread block

    // ---- layer 1 ----
    build_x_kernel<<<(EE * 48 + 255) / 256, 256>>>(ef, nf, ei);
    concat_w_kernel<<<(DIN * DIN + 255) / 256, 256>>>(l1_Wq, l1_Wk, l1_Wv);
    gemm_qkv_kernel<<<gqkv, 256>>>();
    attn_kernel<<<attn_blocks, 256>>>(adj_src);
    gemm_wo_kernel<<<gwo, 256>>>(l1_Wo, ef, nullptr, 0, 1);   // ef_in=edge_features, out=g_ef1

    // ---- layer 2 ----
    update_x_kernel<<<(EE * 16 + 255) / 256, 256>>>();
    concat_w_kernel<<<(DIN * DIN + 255) / 256, 256>>>(l2_Wq, l2_Wk, l2_Wv);
    gemm_qkv_kernel<<<gqkv, 256>>>();
    attn_kernel<<<attn_blocks, 256>>>(adj_src);
    gemm_wo_kernel<<<gwo, 256>>>(l2_Wo, nullptr, out, 1, 0);  // ef_in=g_ef1, out=d_out
}

// round 2
// speedup vs baseline: 1.4678x; 1.4678x over previous
#include <cuda_runtime.h>
#include <stdint.h>

#define EE     100000
#define DIN    192
#define DEDGE  64
#define KNB    8

// ---------------- scratch (device globals) ----------------
__device__ float g_qkv[EE * DIN];    // [E,192] = [q|k|v]
__device__ float g_att[EE * DEDGE];  // [E,64]
__device__ float g_ef1[EE * DEDGE];  // [E,64] layer-1 output

// ---------------- helpers ----------------
__device__ __forceinline__ uint32_t f2tf(float x) {
    uint32_t u; asm("cvt.rna.tf32.f32 %0, %1;" : "=r"(u) : "f"(x)); return u;
}
__device__ __forceinline__ void mma8(float* c, const uint32_t* a, uint32_t b0, uint32_t b1) {
    asm volatile("mma.sync.aligned.m16n8k8.row.col.f32.tf32.tf32.f32 "
        "{%0,%1,%2,%3}, {%4,%5,%6,%7}, {%8,%9}, {%0,%1,%2,%3};"
        : "+f"(c[0]), "+f"(c[1]), "+f"(c[2]), "+f"(c[3])
        : "r"(a[0]), "r"(a[1]), "r"(a[2]), "r"(a[3]), "r"(b0), "r"(b1));
}

// ======================================================================
// QKV GEMM with fused gather:  qkv[:, y*64:y*64+64] = concat(ef|ef1, nf[src], nf[dst]) @ W_y
// BM=128, BN=64, BK=32, 8 warps (4M x 2N), warp tile 32x32, tf32 mma m16n8k8
// ======================================================================
__global__ __launch_bounds__(256, 2) void qkv_mma_kernel(
    const float* __restrict__ ef, const float* __restrict__ nf,
    const int* __restrict__ ei,
    const float* __restrict__ wq, const float* __restrict__ wk, const float* __restrict__ wv,
    int use_ef1)
{
    __shared__ uint32_t As[128 * 36];   // [m][k] m-major, pad 36
    __shared__ uint32_t Bs[64 * 36];    // [n][k] n-major (transposed W tile), pad 36

    const int tid = threadIdx.x;
    const int m0  = blockIdx.x * 128;
    const float* W = (blockIdx.y == 0) ? wq : (blockIdx.y == 1) ? wk : wv;
    const float* efsrc = use_ef1 ? (const float*)g_ef1 : ef;

    // A loader: thread -> (row r, 16-col half kb)
    const int r  = tid >> 1;
    const int e  = m0 + r;
    const int kb = (tid & 1) * 16;
    const bool valid = (e < EE);
    int si = 0, di = 0;
    if (valid) { si = ei[e]; di = ei[EE + e]; }

    // B loader: thread -> (k row bk, 8-col group bn); k-strided for conflict-free transposed STS
    const int bk = tid & 31;
    const int bn = (tid >> 5) * 8;

    const int wid = tid >> 5, lane = tid & 31;
    const int wm = (wid & 3) * 32, wn = (wid >> 2) * 32;
    const int g = lane >> 2, t4 = lane & 3;

    float acc[2][4][4];
    #pragma unroll
    for (int i = 0; i < 2; i++)
        #pragma unroll
        for (int j = 0; j < 4; j++)
            #pragma unroll
            for (int q = 0; q < 4; q++) acc[i][j][q] = 0.f;

    for (int k0 = 0; k0 < DIN; k0 += 32) {
        // ---- global loads (gathered A) ----
        float4 av[4];
        if (valid) {
            const int reg = k0 >> 6;                 // 0: edge feat, 1: nf[src], 2: nf[dst]
            const float* base = (reg == 0) ? efsrc + (size_t)e * 64
                              : (reg == 1) ? nf + (size_t)si * 64
                                           : nf + (size_t)di * 64;
            const int cb = (k0 & 32) + kb;
            #pragma unroll
            for (int c = 0; c < 4; c++) av[c] = *reinterpret_cast<const float4*>(base + cb + c * 4);
        } else {
            #pragma unroll
            for (int c = 0; c < 4; c++) av[c] = make_float4(0.f, 0.f, 0.f, 0.f);
        }
        float4 bv[2];
        #pragma unroll
        for (int c = 0; c < 2; c++)
            bv[c] = *reinterpret_cast<const float4*>(W + (size_t)(k0 + bk) * 64 + bn + c * 4);

        __syncthreads();
        // ---- store A (STS.128, conflict-free) ----
        #pragma unroll
        for (int c = 0; c < 4; c++) {
            uint4 u = make_uint4(f2tf(av[c].x), f2tf(av[c].y), f2tf(av[c].z), f2tf(av[c].w));
            *reinterpret_cast<uint4*>(&As[r * 36 + kb + c * 4]) = u;
        }
        // ---- store B transposed (STS.32, banks = k -> conflict-free) ----
        #pragma unroll
        for (int c = 0; c < 2; c++) {
            float vv[4] = {bv[c].x, bv[c].y, bv[c].z, bv[c].w};
            #pragma unroll
            for (int j = 0; j < 4; j++) Bs[(bn + c * 4 + j) * 36 + bk] = f2tf(vv[j]);
        }
        __syncthreads();

        // ---- compute: 4 k-steps of 8 ----
        #pragma unroll
        for (int ks = 0; ks < 4; ks++) {
            const int k = ks * 8 + t4;
            uint32_t a[2][4];
            #pragma unroll
            for (int mt = 0; mt < 2; mt++) {
                const int m = wm + mt * 16 + g;
                a[mt][0] = As[m * 36 + k];
                a[mt][1] = As[(m + 8) * 36 + k];
                a[mt][2] = As[m * 36 + k + 4];
                a[mt][3] = As[(m + 8) * 36 + k + 4];
            }
            #pragma unroll
            for (int nt = 0; nt < 4; nt++) {
                const int n = wn + nt * 8 + g;
                uint32_t b0 = Bs[n * 36 + k], b1 = Bs[n * 36 + k + 4];
                mma8(acc[0][nt], a[0], b0, b1);
                mma8(acc[1][nt], a[1], b0, b1);
            }
        }
    }

    // ---- epilogue ----
    const int ncb = blockIdx.y * 64 + wn;
    #pragma unroll
    for (int mt = 0; mt < 2; mt++) {
        const int row = m0 + wm + mt * 16 + g;
        #pragma unroll
        for (int nt = 0; nt < 4; nt++) {
            const int col = ncb + nt * 8 + t4 * 2;
            if (row < EE)
                *reinterpret_cast<float2*>(g_qkv + (size_t)row * DIN + col) =
                    make_float2(acc[mt][nt][0], acc[mt][nt][1]);
            if (row + 8 < EE)
                *reinterpret_cast<float2*>(g_qkv + (size_t)(row + 8) * DIN + col) =
                    make_float2(acc[mt][nt][2], acc[mt][nt][3]);
        }
    }
}

// ======================================================================
// Wo GEMM + residual: out = ef_in + g_att[E,64] @ Wo[64,64]   (tf32 mma)
// ======================================================================
__global__ __launch_bounds__(256, 2) void wo_mma_kernel(
    const float* __restrict__ Wo,
    const float* __restrict__ ef_ext, float* __restrict__ out_ext,
    int use_ef1_in, int write_ef1)
{
    __shared__ uint32_t As[128 * 36];
    __shared__ uint32_t Bs[64 * 36];

    const int tid = threadIdx.x;
    const int m0  = blockIdx.x * 128;
    const float* ef_in = use_ef1_in ? (const float*)g_ef1 : ef_ext;
    float* out = write_ef1 ? (float*)g_ef1 : out_ext;

    const int r  = tid >> 1;
    const int e  = m0 + r;
    const int kb = (tid & 1) * 16;
    const bool valid = (e < EE);

    const int bk = tid & 31;
    const int bn = (tid >> 5) * 8;

    const int wid = tid >> 5, lane = tid & 31;
    const int wm = (wid & 3) * 32, wn = (wid >> 2) * 32;
    const int g = lane >> 2, t4 = lane & 3;

    float acc[2][4][4];
    #pragma unroll
    for (int i = 0; i < 2; i++)
        #pragma unroll
        for (int j = 0; j < 4; j++)
            #pragma unroll
            for (int q = 0; q < 4; q++) acc[i][j][q] = 0.f;

    #pragma unroll
    for (int k0 = 0; k0 < 64; k0 += 32) {
        float4 av[4];
        if (valid) {
            const float* base = g_att + (size_t)e * 64 + k0 + kb;
            #pragma unroll
            for (int c = 0; c < 4; c++) av[c] = *reinterpret_cast<const float4*>(base + c * 4);
        } else {
            #pragma unroll
            for (int c = 0; c < 4; c++) av[c] = make_float4(0.f, 0.f, 0.f, 0.f);
        }
        float4 bv[2];
        #pragma unroll
        for (int c = 0; c < 2; c++)
            bv[c] = *reinterpret_cast<const float4*>(Wo + (size_t)(k0 + bk) * 64 + bn + c * 4);

        __syncthreads();
        #pragma unroll
        for (int c = 0; c < 4; c++) {
            uint4 u = make_uint4(f2tf(av[c].x), f2tf(av[c].y), f2tf(av[c].z), f2tf(av[c].w));
            *reinterpret_cast<uint4*>(&As[r * 36 + kb + c * 4]) = u;
        }
        #pragma unroll
        for (int c = 0; c < 2; c++) {
            float vv[4] = {bv[c].x, bv[c].y, bv[c].z, bv[c].w};
            #pragma unroll
            for (int j = 0; j < 4; j++) Bs[(bn + c * 4 + j) * 36 + bk] = f2tf(vv[j]);
        }
        __syncthreads();

        #pragma unroll
        for (int ks = 0; ks < 4; ks++) {
            const int k = ks * 8 + t4;
            uint32_t a[2][4];
            #pragma unroll
            for (int mt = 0; mt < 2; mt++) {
                const int m = wm + mt * 16 + g;
                a[mt][0] = As[m * 36 + k];
                a[mt][1] = As[(m + 8) * 36 + k];
                a[mt][2] = As[m * 36 + k + 4];
                a[mt][3] = As[(m + 8) * 36 + k + 4];
            }
            #pragma unroll
            for (int nt = 0; nt < 4; nt++) {
                const int n = wn + nt * 8 + g;
                uint32_t b0 = Bs[n * 36 + k], b1 = Bs[n * 36 + k + 4];
                mma8(acc[0][nt], a[0], b0, b1);
                mma8(acc[1][nt], a[1], b0, b1);
            }
        }
        __syncthreads();
    }

    // epilogue with residual
    #pragma unroll
    for (int mt = 0; mt < 2; mt++) {
        const int row = m0 + wm + mt * 16 + g;
        #pragma unroll
        for (int nt = 0; nt < 4; nt++) {
            const int col = wn + nt * 8 + t4 * 2;
            if (row < EE) {
                float2 rr = *reinterpret_cast<const float2*>(ef_in + (size_t)row * 64 + col);
                *reinterpret_cast<float2*>(out + (size_t)row * 64 + col) =
                    make_float2(rr.x + acc[mt][nt][0], rr.y + acc[mt][nt][1]);
            }
            if (row + 8 < EE) {
                float2 rr = *reinterpret_cast<const float2*>(ef_in + (size_t)(row + 8) * 64 + col);
                *reinterpret_cast<float2*>(out + (size_t)(row + 8) * 64 + col) =
                    make_float2(rr.x + acc[mt][nt][2], rr.y + acc[mt][nt][3]);
            }
        }
    }
}

// ---------------- attention: one warp per dst edge, K=8 contiguous neighbors ----------------
__global__ void attn_kernel(const int* __restrict__ adj_src) {
    int gw = (blockIdx.x * blockDim.x + threadIdx.x) >> 5;
    int lane = threadIdx.x & 31;
    if (gw >= EE) return;

    const float* qrow = g_qkv + (size_t)gw * DIN;
    float2 q = *reinterpret_cast<const float2*>(qrow + 2 * lane);

    float sj[KNB], v0[KNB], v1[KNB];
    int base = gw * KNB;
    #pragma unroll
    for (int j = 0; j < KNB; j++) {
        int n = adj_src[base + j];
        const float* kr = g_qkv + (size_t)n * DIN + 64;
        float2 kk = *reinterpret_cast<const float2*>(kr + 2 * lane);
        float2 vv = *reinterpret_cast<const float2*>(kr + 64 + 2 * lane);
        float p = q.x * kk.x + q.y * kk.y;
        p += __shfl_xor_sync(0xffffffffu, p, 1);
        p += __shfl_xor_sync(0xffffffffu, p, 2);
        p += __shfl_xor_sync(0xffffffffu, p, 4);   // head-local reduce (8 lanes/head)
        sj[j] = p * 0.25f;                          // 1/sqrt(16)
        v0[j] = vv.x;
        v1[j] = vv.y;
    }

    float m = sj[0];
    #pragma unroll
    for (int j = 1; j < KNB; j++) m = fmaxf(m, sj[j]);

    float denom = 0.f, a0 = 0.f, a1 = 0.f;
    #pragma unroll
    for (int j = 0; j < KNB; j++) {
        float w = __expf(sj[j] - m);
        denom += w;
        a0 += w * v0[j];
        a1 += w * v1[j];
    }
    float inv = 1.0f / denom;
    *reinterpret_cast<float2*>(g_att + (size_t)gw * DEDGE + 2 * lane) =
        make_float2(a0 * inv, a1 * inv);
}

// ---------------- launch ----------------
extern "C" void kernel_launch(void* const* d_in, const int* in_sizes, int n_in,
                              void* d_out, int out_size) {
    const float* nf      = (const float*)d_in[0];
    const float* ef      = (const float*)d_in[1];
    const int*   ei      = (const int*)d_in[2];
    const int*   adj_src = (const int*)d_in[4];
    const float* l1_Wq = (const float*)d_in[6];
    const float* l1_Wk = (const float*)d_in[7];
    const float* l1_Wv = (const float*)d_in[8];
    const float* l1_Wo = (const float*)d_in[9];
    const float* l2_Wq = (const float*)d_in[10];
    const float* l2_Wk = (const float*)d_in[11];
    const float* l2_Wv = (const float*)d_in[12];
    const float* l2_Wo = (const float*)d_in[13];
    float* out = (float*)d_out;

    const dim3 gq((EE + 127) / 128, 3);
    const int gw = (EE + 127) / 128;
    const int attn_blocks = EE / 8;

    // layer 1
    qkv_mma_kernel<<<gq, 256>>>(ef, nf, ei, l1_Wq, l1_Wk, l1_Wv, 0);
    attn_kernel<<<attn_blocks, 256>>>(adj_src);
    wo_mma_kernel<<<gw, 256>>>(l1_Wo, ef, nullptr, 0, 1);

    // layer 2
    qkv_mma_kernel<<<gq, 256>>>(ef, nf, ei, l2_Wq, l2_Wk, l2_Wv, 1);
    attn_kernel<<<attn_blocks, 256>>>(adj_src);
    wo_mma_kernel<<<gw, 256>>>(l2_Wo, nullptr, out, 1, 0);
}

// round 3
// speedup vs baseline: 1.5671x; 1.0676x over previous
#include <cuda_runtime.h>
#include <stdint.h>

#define EE     100000
#define DIN    192
#define KNB    8

// ---------------- scratch (device globals) ----------------
__device__ float g_qkv[EE * DIN];   // [E,192] = [q|k|v]
__device__ float g_att[EE * 64];    // [E,64]
__device__ float g_ef1[EE * 64];    // [E,64] layer-1 out

// ---------------- helpers ----------------
__device__ __forceinline__ uint32_t f2tf(float x) {
    uint32_t u; asm("cvt.rna.tf32.f32 %0, %1;" : "=r"(u) : "f"(x)); return u;
}
__device__ __forceinline__ void mma8(float* c, const uint32_t* a, uint32_t b0, uint32_t b1) {
    asm volatile("mma.sync.aligned.m16n8k8.row.col.f32.tf32.tf32.f32 "
        "{%0,%1,%2,%3}, {%4,%5,%6,%7}, {%8,%9}, {%0,%1,%2,%3};"
        : "+f"(c[0]), "+f"(c[1]), "+f"(c[2]), "+f"(c[3])
        : "r"(a[0]), "r"(a[1]), "r"(a[2]), "r"(a[3]), "r"(b0), "r"(b1));
}
__device__ __forceinline__ void ldsm4(uint32_t* f, uint32_t addr) {
    asm volatile("ldmatrix.sync.aligned.m8n8.x4.shared.b16 {%0,%1,%2,%3}, [%4];"
        : "=r"(f[0]), "=r"(f[1]), "=r"(f[2]), "=r"(f[3]) : "r"(addr));
}

// smem geometry (words): A buf = 128*36, B buf = 64*36, double buffered
#define A_WORDS   (128 * 36)
#define B_WORDS   (64 * 36)
#define SMEM_WORDS (2 * A_WORDS + 2 * B_WORDS)
#define SMEM_BYTES (SMEM_WORDS * 4)

// ======================================================================
// QKV GEMM, fused gather, tf32 mma + ldmatrix + double buffer.
// BM=128, BN=64, BK=32, 8 warps (4M x 2N), warp tile 32x32.
// ======================================================================
__global__ __launch_bounds__(256, 2) void qkv_mma_kernel(
    const float* __restrict__ ef, const float* __restrict__ nf,
    const int* __restrict__ ei,
    const float* __restrict__ wq, const float* __restrict__ wk, const float* __restrict__ wv,
    int use_ef1)
{
    extern __shared__ uint32_t smem[];
    uint32_t* As = smem;                 // [2][128*36]
    uint32_t* Bs = smem + 2 * A_WORDS;   // [2][64*36]

    const int tid = threadIdx.x;
    const int m0  = blockIdx.x * 128;
    const float* W = (blockIdx.y == 0) ? wq : (blockIdx.y == 1) ? wk : wv;
    const float* efsrc = use_ef1 ? (const float*)g_ef1 : ef;

    // A loader: thread -> (row r, 16-col half kb)
    const int r  = tid >> 1;
    const int e  = m0 + r;
    const int kb = (tid & 1) * 16;
    const bool valid = (e < EE);
    int si = 0, di = 0;
    if (valid) { si = ei[e]; di = ei[EE + e]; }

    // B loader: thread -> (k row bk, 8-col group bn)
    const int bk = tid & 31;
    const int bn = (tid >> 5) * 8;

    const int wid = tid >> 5, lane = tid & 31;
    const int wm = (wid & 3) * 32, wn = (wid >> 2) * 32;
    const int g = lane >> 2, t4 = lane & 3;
    const int j8 = lane & 7, grp = lane >> 3;

    // ldmatrix base addresses (byte, buffer 0)
    const uint32_t As_b = (uint32_t)__cvta_generic_to_shared(As);
    const uint32_t Bs_b = (uint32_t)__cvta_generic_to_shared(Bs);
    uint32_t aAddr[2], bAddr[2];
    #pragma unroll
    for (int mt = 0; mt < 2; mt++) {
        int row = wm + mt * 16 + (grp & 1) * 8 + j8;
        int col = (grp >> 1) * 4;
        aAddr[mt] = As_b + (row * 36 + col) * 4;
    }
    #pragma unroll
    for (int p = 0; p < 2; p++) {
        int row = wn + p * 16 + (grp >> 1) * 8 + j8;
        int col = (grp & 1) * 4;
        bAddr[p] = Bs_b + (row * 36 + col) * 4;
    }

    float acc[2][4][4];
    #pragma unroll
    for (int i = 0; i < 2; i++)
        #pragma unroll
        for (int j = 0; j < 4; j++)
            #pragma unroll
            for (int q = 0; q < 4; q++) acc[i][j][q] = 0.f;

    float4 av[4], bv[2];

    // ---- load tile it into registers ----
    auto ldg_tile = [&](int it) {
        const int k0 = it * 32;
        if (valid) {
            const int reg = k0 >> 6;
            const float* base = (reg == 0) ? efsrc + (size_t)e * 64
                              : (reg == 1) ? nf + (size_t)si * 64
                                           : nf + (size_t)di * 64;
            const int cb = (k0 & 32) + kb;
            #pragma unroll
            for (int c = 0; c < 4; c++) av[c] = *reinterpret_cast<const float4*>(base + cb + c * 4);
        } else {
            #pragma unroll
            for (int c = 0; c < 4; c++) av[c] = make_float4(0.f, 0.f, 0.f, 0.f);
        }
        #pragma unroll
        for (int c = 0; c < 2; c++)
            bv[c] = *reinterpret_cast<const float4*>(W + (size_t)(k0 + bk) * 64 + bn + c * 4);
    };
    // ---- store regs to smem buffer b ----
    auto sts_tile = [&](int b) {
        uint32_t* Aw = As + b * A_WORDS;
        uint32_t* Bw = Bs + b * B_WORDS;
        #pragma unroll
        for (int c = 0; c < 4; c++) {
            uint4 u = make_uint4(f2tf(av[c].x), f2tf(av[c].y), f2tf(av[c].z), f2tf(av[c].w));
            *reinterpret_cast<uint4*>(&Aw[r * 36 + kb + c * 4]) = u;
        }
        #pragma unroll
        for (int c = 0; c < 2; c++) {
            float vv[4] = {bv[c].x, bv[c].y, bv[c].z, bv[c].w};
            #pragma unroll
            for (int j = 0; j < 4; j++) Bw[(bn + c * 4 + j) * 36 + bk] = f2tf(vv[j]);
        }
    };

    const int NIT = DIN / 32;   // 6
    ldg_tile(0);
    sts_tile(0);
    ldg_tile(1);
    __syncthreads();

    for (int i = 0; i < NIT; i++) {
        const int cur = i & 1;
        const uint32_t aOff = cur * (A_WORDS * 4);
        const uint32_t bOff = cur * (B_WORDS * 4);
        // compute from buf cur
        #pragma unroll
        for (int ks = 0; ks < 4; ks++) {
            uint32_t af0[4], af1[4], bf0[4], bf1[4];
            ldsm4(af0, aAddr[0] + aOff + ks * 32);
            ldsm4(af1, aAddr[1] + aOff + ks * 32);
            ldsm4(bf0, bAddr[0] + bOff + ks * 32);
            ldsm4(bf1, bAddr[1] + bOff + ks * 32);
            mma8(acc[0][0], af0, bf0[0], bf0[1]);
            mma8(acc[0][1], af0, bf0[2], bf0[3]);
            mma8(acc[0][2], af0, bf1[0], bf1[1]);
            mma8(acc[0][3], af0, bf1[2], bf1[3]);
            mma8(acc[1][0], af1, bf0[0], bf0[1]);
            mma8(acc[1][1], af1, bf0[2], bf0[3]);
            mma8(acc[1][2], af1, bf1[0], bf1[1]);
            mma8(acc[1][3], af1, bf1[2], bf1[3]);
        }
        if (i + 1 < NIT) {
            sts_tile(cur ^ 1);          // regs hold tile i+1
            if (i + 2 < NIT) ldg_tile(i + 2);
            __syncthreads();
        }
    }

    // epilogue
    const int ncb = blockIdx.y * 64 + wn;
    #pragma unroll
    for (int mt = 0; mt < 2; mt++) {
        const int row = m0 + wm + mt * 16 + g;
        #pragma unroll
        for (int nt = 0; nt < 4; nt++) {
            const int col = ncb + nt * 8 + t4 * 2;
            if (row < EE)
                *reinterpret_cast<float2*>(g_qkv + (size_t)row * DIN + col) =
                    make_float2(acc[mt][nt][0], acc[mt][nt][1]);
            if (row + 8 < EE)
                *reinterpret_cast<float2*>(g_qkv + (size_t)(row + 8) * DIN + col) =
                    make_float2(acc[mt][nt][2], acc[mt][nt][3]);
        }
    }
}

// ======================================================================
// Wo GEMM + residual: out = ef_in + g_att[E,64] @ Wo[64,64]
// ======================================================================
__global__ __launch_bounds__(256, 2) void wo_mma_kernel(
    const float* __restrict__ Wo,
    const float* __restrict__ ef_ext, float* __restrict__ out_ext,
    int use_ef1_in, int write_ef1)
{
    extern __shared__ uint32_t smem[];
    uint32_t* As = smem;
    uint32_t* Bs = smem + 2 * A_WORDS;

    const int tid = threadIdx.x;
    const int m0  = blockIdx.x * 128;
    const float* ef_in = use_ef1_in ? (const float*)g_ef1 : ef_ext;
    float* out = write_ef1 ? (float*)g_ef1 : out_ext;

    const int r  = tid >> 1;
    const int e  = m0 + r;
    const int kb = (tid & 1) * 16;
    const bool valid = (e < EE);

    const int bk = tid & 31;
    const int bn = (tid >> 5) * 8;

    const int wid = tid >> 5, lane = tid & 31;
    const int wm = (wid & 3) * 32, wn = (wid >> 2) * 32;
    const int g = lane >> 2, t4 = lane & 3;
    const int j8 = lane & 7, grp = lane >> 3;

    const uint32_t As_b = (uint32_t)__cvta_generic_to_shared(As);
    const uint32_t Bs_b = (uint32_t)__cvta_generic_to_shared(Bs);
    uint32_t aAddr[2], bAddr[2];
    #pragma unroll
    for (int mt = 0; mt < 2; mt++) {
        int row = wm + mt * 16 + (grp & 1) * 8 + j8;
        int col = (grp >> 1) * 4;
        aAddr[mt] = As_b + (row * 36 + col) * 4;
    }
    #pragma unroll
    for (int p = 0; p < 2; p++) {
        int row = wn + p * 16 + (grp >> 1) * 8 + j8;
        int col = (grp & 1) * 4;
        bAddr[p] = Bs_b + (row * 36 + col) * 4;
    }

    float acc[2][4][4];
    #pragma unroll
    for (int i = 0; i < 2; i++)
        #pragma unroll
        for (int j = 0; j < 4; j++)
            #pragma unroll
            for (int q = 0; q < 4; q++) acc[i][j][q] = 0.f;

    float4 av[4], bv[2];
    auto ldg_tile = [&](int it) {
        const int k0 = it * 32;
        if (valid) {
            const float* base = g_att + (size_t)e * 64 + k0 + kb;
            #pragma unroll
            for (int c = 0; c < 4; c++) av[c] = *reinterpret_cast<const float4*>(base + c * 4);
        } else {
            #pragma unroll
            for (int c = 0; c < 4; c++) av[c] = make_float4(0.f, 0.f, 0.f, 0.f);
        }
        #pragma unroll
        for (int c = 0; c < 2; c++)
            bv[c] = *reinterpret_cast<const float4*>(Wo + (size_t)(k0 + bk) * 64 + bn + c * 4);
    };
    auto sts_tile = [&](int b) {
        uint32_t* Aw = As + b * A_WORDS;
        uint32_t* Bw = Bs + b * B_WORDS;
        #pragma unroll
        for (int c = 0; c < 4; c++) {
            uint4 u = make_uint4(f2tf(av[c].x), f2tf(av[c].y), f2tf(av[c].z), f2tf(av[c].w));
            *reinterpret_cast<uint4*>(&Aw[r * 36 + kb + c * 4]) = u;
        }
        #pragma unroll
        for (int c = 0; c < 2; c++) {
            float vv[4] = {bv[c].x, bv[c].y, bv[c].z, bv[c].w};
            #pragma unroll
            for (int j = 0; j < 4; j++) Bw[(bn + c * 4 + j) * 36 + bk] = f2tf(vv[j]);
        }
    };

    ldg_tile(0);
    sts_tile(0);
    ldg_tile(1);
    __syncthreads();

    #pragma unroll
    for (int i = 0; i < 2; i++) {
        const int cur = i & 1;
        const uint32_t aOff = cur * (A_WORDS * 4);
        const uint32_t bOff = cur * (B_WORDS * 4);
        #pragma unroll
        for (int ks = 0; ks < 4; ks++) {
            uint32_t af0[4], af1[4], bf0[4], bf1[4];
            ldsm4(af0, aAddr[0] + aOff + ks * 32);
            ldsm4(af1, aAddr[1] + aOff + ks * 32);
            ldsm4(bf0, bAddr[0] + bOff + ks * 32);
            ldsm4(bf1, bAddr[1] + bOff + ks * 32);
            mma8(acc[0][0], af0, bf0[0], bf0[1]);
            mma8(acc[0][1], af0, bf0[2], bf0[3]);
            mma8(acc[0][2], af0, bf1[0], bf1[1]);
            mma8(acc[0][3], af0, bf1[2], bf1[3]);
            mma8(acc[1][0], af1, bf0[0], bf0[1]);
            mma8(acc[1][1], af1, bf0[2], bf0[3]);
            mma8(acc[1][2], af1, bf1[0], bf1[1]);
            mma8(acc[1][3], af1, bf1[2], bf1[3]);
        }
        if (i == 0) {
            sts_tile(1);
            __syncthreads();
        }
    }

    #pragma unroll
    for (int mt = 0; mt < 2; mt++) {
        const int row = m0 + wm + mt * 16 + g;
        #pragma unroll
        for (int nt = 0; nt < 4; nt++) {
            const int col = wn + nt * 8 + t4 * 2;
            if (row < EE) {
                float2 rr = *reinterpret_cast<const float2*>(ef_in + (size_t)row * 64 + col);
                *reinterpret_cast<float2*>(out + (size_t)row * 64 + col) =
                    make_float2(rr.x + acc[mt][nt][0], rr.y + acc[mt][nt][1]);
            }
            if (row + 8 < EE) {
                float2 rr = *reinterpret_cast<const float2*>(ef_in + (size_t)(row + 8) * 64 + col);
                *reinterpret_cast<float2*>(out + (size_t)(row + 8) * 64 + col) =
                    make_float2(rr.x + acc[mt][nt][2], rr.y + acc[mt][nt][3]);
            }
        }
    }
}

// ---------------- attention: one warp per dst edge ----------------
__global__ void attn_kernel(const int* __restrict__ adj_src) {
    int gw = (blockIdx.x * blockDim.x + threadIdx.x) >> 5;
    int lane = threadIdx.x & 31;
    if (gw >= EE) return;

    const float* qrow = g_qkv + (size_t)gw * DIN;
    float2 q = *reinterpret_cast<const float2*>(qrow + 2 * lane);

    float sj[KNB], v0[KNB], v1[KNB];
    int base = gw * KNB;
    #pragma unroll
    for (int j = 0; j < KNB; j++) {
        int n = adj_src[base + j];
        const float* kr = g_qkv + (size_t)n * DIN + 64;
        float2 kk = *reinterpret_cast<const float2*>(kr + 2 * lane);
        float2 vv = *reinterpret_cast<const float2*>(kr + 64 + 2 * lane);
        float p = q.x * kk.x + q.y * kk.y;
        p += __shfl_xor_sync(0xffffffffu, p, 1);
        p += __shfl_xor_sync(0xffffffffu, p, 2);
        p += __shfl_xor_sync(0xffffffffu, p, 4);
        sj[j] = p * 0.25f;
        v0[j] = vv.x;
        v1[j] = vv.y;
    }

    float m = sj[0];
    #pragma unroll
    for (int j = 1; j < KNB; j++) m = fmaxf(m, sj[j]);

    float denom = 0.f, a0 = 0.f, a1 = 0.f;
    #pragma unroll
    for (int j = 0; j < KNB; j++) {
        float w = __expf(sj[j] - m);
        denom += w;
        a0 += w * v0[j];
        a1 += w * v1[j];
    }
    float inv = 1.0f / denom;
    *reinterpret_cast<float2*>(g_att + (size_t)gw * 64 + 2 * lane) =
        make_float2(a0 * inv, a1 * inv);
}

// ---------------- launch ----------------
extern "C" void kernel_launch(void* const* d_in, const int* in_sizes, int n_in,
                              void* d_out, int out_size) {
    const float* nf      = (const float*)d_in[0];
    const float* ef      = (const float*)d_in[1];
    const int*   ei      = (const int*)d_in[2];
    const int*   adj_src = (const int*)d_in[4];
    const float* l1_Wq = (const float*)d_in[6];
    const float* l1_Wk = (const float*)d_in[7];
    const float* l1_Wv = (const float*)d_in[8];
    const float* l1_Wo = (const float*)d_in[9];
    const float* l2_Wq = (const float*)d_in[10];
    const float* l2_Wk = (const float*)d_in[11];
    const float* l2_Wv = (const float*)d_in[12];
    const float* l2_Wo = (const float*)d_in[13];
    float* out = (float*)d_out;

    static int attr_done = 0;
    if (!attr_done) {
        cudaFuncSetAttribute(qkv_mma_kernel, cudaFuncAttributeMaxDynamicSharedMemorySize, SMEM_BYTES);
        cudaFuncSetAttribute(wo_mma_kernel,  cudaFuncAttributeMaxDynamicSharedMemorySize, SMEM_BYTES);
        attr_done = 1;
    }

    const dim3 gq((EE + 127) / 128, 3);
    const int gw = (EE + 127) / 128;
    const int attn_blocks = EE / 8;

    // layer 1
    qkv_mma_kernel<<<gq, 256, SMEM_BYTES>>>(ef, nf, ei, l1_Wq, l1_Wk, l1_Wv, 0);
    attn_kernel<<<attn_blocks, 256>>>(adj_src);
    wo_mma_kernel<<<gw, 256, SMEM_BYTES>>>(l1_Wo, ef, nullptr, 0, 1);

    // layer 2
    qkv_mma_kernel<<<gq, 256, SMEM_BYTES>>>(ef, nf, ei, l2_Wq, l2_Wk, l2_Wv, 1);
    attn_kernel<<<attn_blocks, 256>>>(adj_src);
    wo_mma_kernel<<<gw, 256, SMEM_BYTES>>>(l2_Wo, nullptr, out, 1, 0);
}

// round 4
// speedup vs baseline: 1.9779x; 1.2622x over previous
#include <cuda_runtime.h>
#include <stdint.h>

#define EE     100000
#define DIN    192
#define KNB    8

// ---------------- scratch (device globals) ----------------
__device__ float g_qkv[EE * DIN];   // [E,192] = [q|k|v]
__device__ float g_att[EE * 64];    // [E,64]
__device__ float g_ef1[EE * 64];    // [E,64] layer-1 out

// ---------------- helpers ----------------
__device__ __forceinline__ uint32_t f2tf(float x) {
    uint32_t u; asm("cvt.rna.tf32.f32 %0, %1;" : "=r"(u) : "f"(x)); return u;
}
__device__ __forceinline__ void mma8(float* c, const uint32_t* a, uint32_t b0, uint32_t b1) {
    asm volatile("mma.sync.aligned.m16n8k8.row.col.f32.tf32.tf32.f32 "
        "{%0,%1,%2,%3}, {%4,%5,%6,%7}, {%8,%9}, {%0,%1,%2,%3};"
        : "+f"(c[0]), "+f"(c[1]), "+f"(c[2]), "+f"(c[3])
        : "r"(a[0]), "r"(a[1]), "r"(a[2]), "r"(a[3]), "r"(b0), "r"(b1));
}
__device__ __forceinline__ void ldsm4(uint32_t* f, uint32_t addr) {
    asm volatile("ldmatrix.sync.aligned.m8n8.x4.shared.b16 {%0,%1,%2,%3}, [%4];"
        : "=r"(f[0]), "=r"(f[1]), "=r"(f[2]), "=r"(f[3]) : "r"(addr));
}

// ---------------- QKV kernel smem geometry ----------------
// B full-resident: [k=192][n=192] stride 200 (200 % 32 == 8 -> conflict-free frag LDS)
// A tile: [m=128][k=32] stride 36, double buffered
#define BSTRIDE    200
#define B_WORDS_F  (192 * BSTRIDE)      // 38400
#define A_WORDS    (128 * 36)           // 4608
#define QKV_SMEM_WORDS (B_WORDS_F + 2 * A_WORDS)
#define QKV_SMEM_BYTES (QKV_SMEM_WORDS * 4)

// Wo kernel smem (round-3 layout)
#define WA_WORDS   (128 * 36)
#define WB_WORDS   (64 * 36)
#define WO_SMEM_BYTES ((2 * WA_WORDS + 2 * WB_WORDS) * 4)

// ======================================================================
// Fused QKV GEMM: qkv[E,192] = concat(ef|ef1, nf[src], nf[dst]) @ [Wq|Wk|Wv]
// BM=128, BN=192, BK=32; 8 warps as 2M x 4N, warp tile 64x48.
// ======================================================================
__global__ __launch_bounds__(256, 1) void qkv_mma_kernel(
    const float* __restrict__ ef, const float* __restrict__ nf,
    const int* __restrict__ ei,
    const float* __restrict__ wq, const float* __restrict__ wk, const float* __restrict__ wv,
    int use_ef1)
{
    extern __shared__ uint32_t smem[];
    uint32_t* Bs = smem;                 // [192][200]
    uint32_t* As = smem + B_WORDS_F;     // [2][128*36]

    const int tid = threadIdx.x;
    const int m0  = blockIdx.x * 128;
    const float* efsrc = use_ef1 ? (const float*)g_ef1 : ef;

    // ---- A loader: thread -> (row r, 16-col half kb) ----
    const int r  = tid >> 1;
    const int e  = m0 + r;
    const int kb = (tid & 1) * 16;
    const bool valid = (e < EE);
    int si = 0, di = 0;
    if (valid) { si = ei[e]; di = ei[EE + e]; }

    const int wid = tid >> 5, lane = tid & 31;
    const int wm = (wid & 1) * 64, wn = (wid >> 1) * 48;
    const int g = lane >> 2, t4 = lane & 3;
    const int j8 = lane & 7, grp = lane >> 3;

    // ---- preload full B into smem (converted to tf32) ----
    {
        #pragma unroll
        for (int w = 0; w < 3; w++) {
            const float* W = (w == 0) ? wq : (w == 1) ? wk : wv;
            #pragma unroll
            for (int j = 0; j < 12; j++) {
                int f = j * 256 + tid;          // float4 index within this W
                int k = f >> 4;                 // 16 float4 per k-row
                int n4 = (f & 15) * 4;
                float4 v = *reinterpret_cast<const float4*>(W + (size_t)k * 64 + n4);
                uint32_t* dst = Bs + k * BSTRIDE + w * 64 + n4;
                dst[0] = f2tf(v.x); dst[1] = f2tf(v.y);
                dst[2] = f2tf(v.z); dst[3] = f2tf(v.w);
            }
        }
    }

    // ---- ldmatrix A base addresses ----
    const uint32_t As_b = (uint32_t)__cvta_generic_to_shared(As);
    uint32_t aAddr[4];
    #pragma unroll
    for (int mt = 0; mt < 4; mt++) {
        int row = wm + mt * 16 + (grp & 1) * 8 + j8;
        int col = (grp >> 1) * 4;
        aAddr[mt] = As_b + (row * 36 + col) * 4;
    }

    float acc[4][6][4];
    #pragma unroll
    for (int i = 0; i < 4; i++)
        #pragma unroll
        for (int j = 0; j < 6; j++)
            #pragma unroll
            for (int q = 0; q < 4; q++) acc[i][j][q] = 0.f;

    float4 av[4];
    auto ldg_tile = [&](int it) {
        const int k0 = it * 32;
        if (valid) {
            const int reg = k0 >> 6;
            const float* base = (reg == 0) ? efsrc + (size_t)e * 64
                              : (reg == 1) ? nf + (size_t)si * 64
                                           : nf + (size_t)di * 64;
            const int cb = (k0 & 32) + kb;
            #pragma unroll
            for (int c = 0; c < 4; c++) av[c] = *reinterpret_cast<const float4*>(base + cb + c * 4);
        } else {
            #pragma unroll
            for (int c = 0; c < 4; c++) av[c] = make_float4(0.f, 0.f, 0.f, 0.f);
        }
    };
    auto sts_tile = [&](int b) {
        uint32_t* Aw = As + b * A_WORDS;
        #pragma unroll
        for (int c = 0; c < 4; c++) {
            uint4 u = make_uint4(f2tf(av[c].x), f2tf(av[c].y), f2tf(av[c].z), f2tf(av[c].w));
            *reinterpret_cast<uint4*>(&Aw[r * 36 + kb + c * 4]) = u;
        }
    };

    const uint32_t* Bwp = Bs + wn + g;   // per-thread B column base

    const int NIT = DIN / 32;   // 6
    ldg_tile(0);
    sts_tile(0);
    ldg_tile(1);
    __syncthreads();

    for (int i = 0; i < NIT; i++) {
        const int cur = i & 1;
        const uint32_t aOff = cur * (A_WORDS * 4);
        #pragma unroll
        for (int ks = 0; ks < 4; ks++) {
            const int kg = i * 32 + ks * 8 + t4;     // global k for B
            uint32_t af[4][4];
            #pragma unroll
            for (int mt = 0; mt < 4; mt++) ldsm4(af[mt], aAddr[mt] + aOff + ks * 32);
            uint32_t b0[6], b1[6];
            #pragma unroll
            for (int nt = 0; nt < 6; nt++) {
                b0[nt] = Bwp[kg * BSTRIDE + nt * 8];
                b1[nt] = Bwp[(kg + 4) * BSTRIDE + nt * 8];
            }
            #pragma unroll
            for (int mt = 0; mt < 4; mt++)
                #pragma unroll
                for (int nt = 0; nt < 6; nt++)
                    mma8(acc[mt][nt], af[mt], b0[nt], b1[nt]);
        }
        if (i + 1 < NIT) {
            sts_tile(cur ^ 1);              // regs hold tile i+1
            if (i + 2 < NIT) ldg_tile(i + 2);
            __syncthreads();
        }
    }

    // ---- epilogue ----
    #pragma unroll
    for (int mt = 0; mt < 4; mt++) {
        const int row = m0 + wm + mt * 16 + g;
        #pragma unroll
        for (int nt = 0; nt < 6; nt++) {
            const int col = wn + nt * 8 + t4 * 2;
            if (row < EE)
                *reinterpret_cast<float2*>(g_qkv + (size_t)row * DIN + col) =
                    make_float2(acc[mt][nt][0], acc[mt][nt][1]);
            if (row + 8 < EE)
                *reinterpret_cast<float2*>(g_qkv + (size_t)(row + 8) * DIN + col) =
                    make_float2(acc[mt][nt][2], acc[mt][nt][3]);
        }
    }
}

// ======================================================================
// Wo GEMM + residual: out = ef_in + g_att[E,64] @ Wo[64,64]  (round-3 design)
// ======================================================================
__global__ __launch_bounds__(256, 2) void wo_mma_kernel(
    const float* __restrict__ Wo,
    const float* __restrict__ ef_ext, float* __restrict__ out_ext,
    int use_ef1_in, int write_ef1)
{
    extern __shared__ uint32_t smem[];
    uint32_t* As = smem;
    uint32_t* Bs = smem + 2 * WA_WORDS;

    const int tid = threadIdx.x;
    const int m0  = blockIdx.x * 128;
    const float* ef_in = use_ef1_in ? (const float*)g_ef1 : ef_ext;
    float* out = write_ef1 ? (float*)g_ef1 : out_ext;

    const int r  = tid >> 1;
    const int e  = m0 + r;
    const int kb = (tid & 1) * 16;
    const bool valid = (e < EE);

    const int bk = tid & 31;
    const int bn = (tid >> 5) * 8;

    const int wid = tid >> 5, lane = tid & 31;
    const int wm = (wid & 3) * 32, wn = (wid >> 2) * 32;
    const int g = lane >> 2, t4 = lane & 3;
    const int j8 = lane & 7, grp = lane >> 3;

    const uint32_t As_b = (uint32_t)__cvta_generic_to_shared(As);
    const uint32_t Bs_b = (uint32_t)__cvta_generic_to_shared(Bs);
    uint32_t aAddr[2], bAddr[2];
    #pragma unroll
    for (int mt = 0; mt < 2; mt++) {
        int row = wm + mt * 16 + (grp & 1) * 8 + j8;
        int col = (grp >> 1) * 4;
        aAddr[mt] = As_b + (row * 36 + col) * 4;
    }
    #pragma unroll
    for (int p = 0; p < 2; p++) {
        int row = wn + p * 16 + (grp >> 1) * 8 + j8;
        int col = (grp & 1) * 4;
        bAddr[p] = Bs_b + (row * 36 + col) * 4;
    }

    float acc[2][4][4];
    #pragma unroll
    for (int i = 0; i < 2; i++)
        #pragma unroll
        for (int j = 0; j < 4; j++)
            #pragma unroll
            for (int q = 0; q < 4; q++) acc[i][j][q] = 0.f;

    float4 av[4], bv[2];
    auto ldg_tile = [&](int it) {
        const int k0 = it * 32;
        if (valid) {
            const float* base = g_att + (size_t)e * 64 + k0 + kb;
            #pragma unroll
            for (int c = 0; c < 4; c++) av[c] = *reinterpret_cast<const float4*>(base + c * 4);
        } else {
            #pragma unroll
            for (int c = 0; c < 4; c++) av[c] = make_float4(0.f, 0.f, 0.f, 0.f);
        }
        #pragma unroll
        for (int c = 0; c < 2; c++)
            bv[c] = *reinterpret_cast<const float4*>(Wo + (size_t)(k0 + bk) * 64 + bn + c * 4);
    };
    auto sts_tile = [&](int b) {
        uint32_t* Aw = As + b * WA_WORDS;
        uint32_t* Bw = Bs + b * WB_WORDS;
        #pragma unroll
        for (int c = 0; c < 4; c++) {
            uint4 u = make_uint4(f2tf(av[c].x), f2tf(av[c].y), f2tf(av[c].z), f2tf(av[c].w));
            *reinterpret_cast<uint4*>(&Aw[r * 36 + kb + c * 4]) = u;
        }
        #pragma unroll
        for (int c = 0; c < 2; c++) {
            float vv[4] = {bv[c].x, bv[c].y, bv[c].z, bv[c].w};
            #pragma unroll
            for (int j = 0; j < 4; j++) Bw[(bn + c * 4 + j) * 36 + bk] = f2tf(vv[j]);
        }
    };

    ldg_tile(0);
    sts_tile(0);
    ldg_tile(1);
    __syncthreads();

    #pragma unroll
    for (int i = 0; i < 2; i++) {
        const int cur = i & 1;
        const uint32_t aOff = cur * (WA_WORDS * 4);
        const uint32_t bOff = cur * (WB_WORDS * 4);
        #pragma unroll
        for (int ks = 0; ks < 4; ks++) {
            uint32_t af0[4], af1[4], bf0[4], bf1[4];
            ldsm4(af0, aAddr[0] + aOff + ks * 32);
            ldsm4(af1, aAddr[1] + aOff + ks * 32);
            ldsm4(bf0, bAddr[0] + bOff + ks * 32);
            ldsm4(bf1, bAddr[1] + bOff + ks * 32);
            mma8(acc[0][0], af0, bf0[0], bf0[1]);
            mma8(acc[0][1], af0, bf0[2], bf0[3]);
            mma8(acc[0][2], af0, bf1[0], bf1[1]);
            mma8(acc[0][3], af0, bf1[2], bf1[3]);
            mma8(acc[1][0], af1, bf0[0], bf0[1]);
            mma8(acc[1][1], af1, bf0[2], bf0[3]);
            mma8(acc[1][2], af1, bf1[0], bf1[1]);
            mma8(acc[1][3], af1, bf1[2], bf1[3]);
        }
        if (i == 0) {
            sts_tile(1);
            __syncthreads();
        }
    }

    #pragma unroll
    for (int mt = 0; mt < 2; mt++) {
        const int row = m0 + wm + mt * 16 + g;
        #pragma unroll
        for (int nt = 0; nt < 4; nt++) {
            const int col = wn + nt * 8 + t4 * 2;
            if (row < EE) {
                float2 rr = *reinterpret_cast<const float2*>(ef_in + (size_t)row * 64 + col);
                *reinterpret_cast<float2*>(out + (size_t)row * 64 + col) =
                    make_float2(rr.x + acc[mt][nt][0], rr.y + acc[mt][nt][1]);
            }
            if (row + 8 < EE) {
                float2 rr = *reinterpret_cast<const float2*>(ef_in + (size_t)(row + 8) * 64 + col);
                *reinterpret_cast<float2*>(out + (size_t)(row + 8) * 64 + col) =
                    make_float2(rr.x + acc[mt][nt][2], rr.y + acc[mt][nt][3]);
            }
        }
    }
}

// ---------------- attention: one warp per dst edge ----------------
__global__ void attn_kernel(const int* __restrict__ adj_src) {
    int gw = (blockIdx.x * blockDim.x + threadIdx.x) >> 5;
    int lane = threadIdx.x & 31;
    if (gw >= EE) return;

    const float* qrow = g_qkv + (size_t)gw * DIN;
    float2 q = *reinterpret_cast<const float2*>(qrow + 2 * lane);

    float sj[KNB], v0[KNB], v1[KNB];
    int base = gw * KNB;
    #pragma unroll
    for (int j = 0; j < KNB; j++) {
        int n = adj_src[base + j];
        const float* kr = g_qkv + (size_t)n * DIN + 64;
        float2 kk = *reinterpret_cast<const float2*>(kr + 2 * lane);
        float2 vv = *reinterpret_cast<const float2*>(kr + 64 + 2 * lane);
        float p = q.x * kk.x + q.y * kk.y;
        p += __shfl_xor_sync(0xffffffffu, p, 1);
        p += __shfl_xor_sync(0xffffffffu, p, 2);
        p += __shfl_xor_sync(0xffffffffu, p, 4);
        sj[j] = p * 0.25f;
        v0[j] = vv.x;
        v1[j] = vv.y;
    }

    float m = sj[0];
    #pragma unroll
    for (int j = 1; j < KNB; j++) m = fmaxf(m, sj[j]);

    float denom = 0.f, a0 = 0.f, a1 = 0.f;
    #pragma unroll
    for (int j = 0; j < KNB; j++) {
        float w = __expf(sj[j] - m);
        denom += w;
        a0 += w * v0[j];
        a1 += w * v1[j];
    }
    float inv = 1.0f / denom;
    *reinterpret_cast<float2*>(g_att + (size_t)gw * 64 + 2 * lane) =
        make_float2(a0 * inv, a1 * inv);
}

// ---------------- launch ----------------
extern "C" void kernel_launch(void* const* d_in, const int* in_sizes, int n_in,
                              void* d_out, int out_size) {
    const float* nf      = (const float*)d_in[0];
    const float* ef      = (const float*)d_in[1];
    const int*   ei      = (const int*)d_in[2];
    const int*   adj_src = (const int*)d_in[4];
    const float* l1_Wq = (const float*)d_in[6];
    const float* l1_Wk = (const float*)d_in[7];
    const float* l1_Wv = (const float*)d_in[8];
    const float* l1_Wo = (const float*)d_in[9];
    const float* l2_Wq = (const float*)d_in[10];
    const float* l2_Wk = (const float*)d_in[11];
    const float* l2_Wv = (const float*)d_in[12];
    const float* l2_Wo = (const float*)d_in[13];
    float* out = (float*)d_out;

    static int attr_done = 0;
    if (!attr_done) {
        cudaFuncSetAttribute(qkv_mma_kernel, cudaFuncAttributeMaxDynamicSharedMemorySize, QKV_SMEM_BYTES);
        cudaFuncSetAttribute(wo_mma_kernel,  cudaFuncAttributeMaxDynamicSharedMemorySize, WO_SMEM_BYTES);
        attr_done = 1;
    }

    const int gq = (EE + 127) / 128;
    const int gw = (EE + 127) / 128;
    const int attn_blocks = EE / 8;

    // layer 1
    qkv_mma_kernel<<<gq, 256, QKV_SMEM_BYTES>>>(ef, nf, ei, l1_Wq, l1_Wk, l1_Wv, 0);
    attn_kernel<<<attn_blocks, 256>>>(adj_src);
    wo_mma_kernel<<<gw, 256, WO_SMEM_BYTES>>>(l1_Wo, ef, nullptr, 0, 1);

    // layer 2
    qkv_mma_kernel<<<gq, 256, QKV_SMEM_BYTES>>>(ef, nf, ei, l2_Wq, l2_Wk, l2_Wv, 1);
    attn_kernel<<<attn_blocks, 256>>>(adj_src);
    wo_mma_kernel<<<gw, 256, WO_SMEM_BYTES>>>(l2_Wo, nullptr, out, 1, 0);
}